// round 5
// baseline (speedup 1.0000x reference)
#include <cuda_runtime.h>
#include <math.h>
#include <stdint.h>

namespace {
constexpr int B_  = 128;
constexpr int T_  = 288;
constexpr int FC_ = 16;
constexpr int FO_ = 64;
constexpr int U_  = 256;
constexpr int H_  = 4;
constexpr int HD_ = 64;
constexpr int BT_ = B_ * T_;          // 36864
constexpr float EPS_ = 1e-6f;
}

// ---------------- device scratch (static, no runtime alloc) ----------------
__device__ float g_x [BT_ * U_];
__device__ float g_xg[BT_ * 3 * U_];      // GRU input gates; later aliased as q/k/v
__device__ float g_g [BT_ * U_];
__device__ float g_a [BT_ * U_];
__device__ float g_s [(long long)B_ * H_ * T_ * T_];
__device__ float g_c [B_ * (U_ + FO_)];
__device__ float g_h1[B_ * 128];
__device__ float g_h2[B_ * 64];
__device__ float4 g_wt4[U_ * U_];         // repacked Wh: [k][u] -> (wr,wz,wn,0)

// ---------------- helpers ----------------
template<int NW, bool DOMAX>
__device__ __forceinline__ float blk_red(float v, float* sh) {
#pragma unroll
    for (int o = 16; o > 0; o >>= 1) {
        float t = __shfl_down_sync(0xffffffffu, v, o);
        v = DOMAX ? fmaxf(v, t) : v + t;
    }
    if ((threadIdx.x & 31) == 0) sh[threadIdx.x >> 5] = v;
    __syncthreads();
    if (threadIdx.x == 0) {
        float t = sh[0];
#pragma unroll
        for (int w = 1; w < NW; w++) t = DOMAX ? fmaxf(t, sh[w]) : t + sh[w];
        sh[0] = t;
    }
    __syncthreads();
    float r = sh[0];
    __syncthreads();
    return r;
}

__device__ __forceinline__ float warp_sum(float v) {
#pragma unroll
    for (int o = 16; o > 0; o >>= 1) v += __shfl_xor_sync(0xffffffffu, v, o);
    return v;
}
__device__ __forceinline__ float warp_max(float v) {
#pragma unroll
    for (int o = 16; o > 0; o >>= 1) v = fmaxf(v, __shfl_xor_sync(0xffffffffu, v, o));
    return v;
}

__device__ __forceinline__ float sigmoidf_(float x) {
    return 1.0f / (1.0f + expf(-x));
}

__device__ __forceinline__ uint32_t f2tf(float x) {
    uint32_t r;
    asm("cvt.rna.tf32.f32 %0, %1;" : "=r"(r) : "f"(x));
    return r;
}
__device__ __forceinline__ uint4 cvt4(float4 v) {
    uint4 o;
    o.x = f2tf(v.x); o.y = f2tf(v.y); o.z = f2tf(v.z); o.w = f2tf(v.w);
    return o;
}
__device__ __forceinline__ void mma_tf32(float* c, const uint32_t* a, const uint32_t* b) {
    asm volatile(
        "mma.sync.aligned.m16n8k8.row.col.f32.tf32.tf32.f32 "
        "{%0,%1,%2,%3}, {%4,%5,%6,%7}, {%8,%9}, {%0,%1,%2,%3};"
        : "+f"(c[0]), "+f"(c[1]), "+f"(c[2]), "+f"(c[3])
        : "r"(a[0]), "r"(a[1]), "r"(a[2]), "r"(a[3]), "r"(b[0]), "r"(b[1]));
}

// ---------------- tf32 tensor-core GEMM ----------------
// C[M,N] = alpha * A[M,K] @ op(B) (+ bias[n]).  op(B)=B[K,N] (TB=false) or
// op(B)=Bmat[N,K]^T (TB=true).  Batched via blockIdx.z with z = 4*b + h.
// Tile: 128(M) x 64(N) x 32(K), 256 threads, warp grid 4x2, warp tile 32x32.
template<bool TB, bool BIAS>
__global__ void __launch_bounds__(256) gemm_tf32(
    const float* __restrict__ A, const float* __restrict__ Bm,
    const float* __restrict__ bias, float* __restrict__ C,
    int M, int N, int K, int lda, int ldb, int ldc,
    long long sAb, long long sAh, long long sBb, long long sBh,
    long long sCb, long long sCh, float alpha)
{
    __shared__ uint32_t As[128 * 36];   // [m][k], stride 36 (bank-clean)
    __shared__ uint32_t Bs[32 * 72];    // [k][n], stride 72 (bank-clean)

    int z = blockIdx.z, zb = z >> 2, zh = z & 3;
    A  += (long long)zb * sAb + (long long)zh * sAh;
    Bm += (long long)zb * sBb + (long long)zh * sBh;
    C  += (long long)zb * sCb + (long long)zh * sCh;

    int tid  = threadIdx.x;
    int lane = tid & 31, warp = tid >> 5;
    int wm = (warp >> 1) * 32, wn = (warp & 1) * 32;
    int g = lane >> 2, l4 = lane & 3;
    int m0 = blockIdx.y * 128, n0 = blockIdx.x * 64;

    float acc[2][4][4];
#pragma unroll
    for (int mi = 0; mi < 2; mi++)
#pragma unroll
        for (int ni = 0; ni < 4; ni++)
#pragma unroll
            for (int q = 0; q < 4; q++) acc[mi][ni][q] = 0.f;

    int arow = tid >> 3;             // 0..31
    int akq  = (tid & 7) * 4;        // 0,4,...,28

    for (int k0 = 0; k0 < K; k0 += 32) {
        // ---- A tile [128][32] -> As[m][k] ----
#pragma unroll
        for (int p = 0; p < 4; p++) {
            int mloc = arow + 32 * p;
            int m = m0 + mloc, k = k0 + akq;
            float4 v = make_float4(0.f, 0.f, 0.f, 0.f);
            if (m < M && k < K) v = *(const float4*)(A + (long long)m * lda + k);
            *(uint4*)&As[mloc * 36 + akq] = cvt4(v);
        }
        // ---- B tile [32][64] -> Bs[k][n] ----
        if (!TB) {
            int bn4 = (tid & 15) * 4, bkr = tid >> 4;  // 0..15
#pragma unroll
            for (int p = 0; p < 2; p++) {
                int kloc = bkr + 16 * p;
                int k = k0 + kloc, n = n0 + bn4;
                float4 v = make_float4(0.f, 0.f, 0.f, 0.f);
                if (k < K && n < N) v = *(const float4*)(Bm + (long long)k * ldb + n);
                *(uint4*)&Bs[kloc * 72 + bn4] = cvt4(v);
            }
        } else {
            int tn = tid & 63, tkq = (tid >> 6) * 4;   // 0,4,8,12
#pragma unroll
            for (int p = 0; p < 2; p++) {
                int kloc = tkq + 16 * p;
                int n = n0 + tn, k = k0 + kloc;
                float4 v = make_float4(0.f, 0.f, 0.f, 0.f);
                if (n < N && k < K) v = *(const float4*)(Bm + (long long)n * ldb + k);
                Bs[(kloc + 0) * 72 + tn] = f2tf(v.x);
                Bs[(kloc + 1) * 72 + tn] = f2tf(v.y);
                Bs[(kloc + 2) * 72 + tn] = f2tf(v.z);
                Bs[(kloc + 3) * 72 + tn] = f2tf(v.w);
            }
        }
        __syncthreads();

#pragma unroll
        for (int kk = 0; kk < 32; kk += 8) {
            uint32_t af[2][4];
#pragma unroll
            for (int mi = 0; mi < 2; mi++) {
                int r = wm + 16 * mi + g;
                af[mi][0] = As[r * 36 + kk + l4];
                af[mi][1] = As[(r + 8) * 36 + kk + l4];
                af[mi][2] = As[r * 36 + kk + l4 + 4];
                af[mi][3] = As[(r + 8) * 36 + kk + l4 + 4];
            }
            uint32_t bf[4][2];
#pragma unroll
            for (int ni = 0; ni < 4; ni++) {
                int c = wn + 8 * ni + g;
                bf[ni][0] = Bs[(kk + l4) * 72 + c];
                bf[ni][1] = Bs[(kk + l4 + 4) * 72 + c];
            }
#pragma unroll
            for (int mi = 0; mi < 2; mi++)
#pragma unroll
                for (int ni = 0; ni < 4; ni++)
                    mma_tf32(acc[mi][ni], af[mi], bf[ni]);
        }
        __syncthreads();
    }

    // ---- epilogue ----
#pragma unroll
    for (int mi = 0; mi < 2; mi++) {
#pragma unroll
        for (int ni = 0; ni < 4; ni++) {
            int m = m0 + wm + 16 * mi + g;
            int n = n0 + wn + 8 * ni + 2 * l4;
            if (n >= N) continue;
            float b0v = 0.f, b1v = 0.f;
            if (BIAS) { b0v = bias[n]; b1v = bias[n + 1]; }
            float* cc = acc[mi][ni];
            if (m < M) {
                float2 o = make_float2(cc[0] * alpha + b0v, cc[1] * alpha + b1v);
                *(float2*)(C + (long long)m * ldc + n) = o;
            }
            if (m + 8 < M) {
                float2 o = make_float2(cc[2] * alpha + b0v, cc[3] * alpha + b1v);
                *(float2*)(C + (long long)(m + 8) * ldc + n) = o;
            }
        }
    }
}

// ---------------- layer norm, warp-per-row (U=256) ----------------
// mode 0: out = LN(a) + res ; mode 1: out = LN(a + res) ; mode 2: out = LN(a)
__global__ void __launch_bounds__(256) ln_kernel(
    const float* __restrict__ a, const float* __restrict__ res,
    const float* __restrict__ s, const float* __restrict__ bb,
    float* __restrict__ out, int mode)
{
    int lane = threadIdx.x & 31;
    long long row = (long long)blockIdx.x * 8 + (threadIdx.x >> 5);
    const float* pa = a + row * U_;
    const float* pr = res + row * U_;
    float* po = out + row * U_;

    float xv[8], rv[8];
    float sum = 0.f;
#pragma unroll
    for (int j = 0; j < 8; j++) {
        int u = lane + 32 * j;
        float v = pa[u];
        float r = (mode == 2) ? 0.f : pr[u];
        rv[j] = r;
        xv[j] = (mode == 1) ? v + r : v;
        sum += xv[j];
    }
    float m = warp_sum(sum) * (1.f / U_);
    float vs = 0.f;
#pragma unroll
    for (int j = 0; j < 8; j++) { float d = xv[j] - m; vs += d * d; }
    float rstd = rsqrtf(warp_sum(vs) * (1.f / U_) + EPS_);
#pragma unroll
    for (int j = 0; j < 8; j++) {
        int u = lane + 32 * j;
        float y = (xv[j] - m) * rstd * s[u] + bb[u];
        if (mode == 0) y += rv[j];
        po[u] = y;
    }
}

// ---------------- repack Wh -> float4 [k][u] ----------------
__global__ void repack_wh_kernel(const float* __restrict__ Wh)
{
    int k = blockIdx.x, u = threadIdx.x;
    g_wt4[k * U_ + u] = make_float4(Wh[k * 768 + u],
                                    Wh[k * 768 + 256 + u],
                                    Wh[k * 768 + 512 + u], 0.f);
}

// ---------------- GRU single time step ----------------
// grid (16,8): 8 batch rows x 32 u per CTA; thread = (b,u); w via packed float4.
__global__ void __launch_bounds__(256) gru_step_kernel(
    const float* __restrict__ bhn, int t)
{
    __shared__ float hsh[8][256];
    int tid = threadIdx.x;
    int bl = tid >> 5, ul = tid & 31;
    int b0 = blockIdx.x * 8;
    int u = blockIdx.y * 32 + ul;

    if (t > 0) {
        const float* hp = g_g + ((long long)b0 * T_ + (t - 1)) * U_;
#pragma unroll
        for (int i = 0; i < 2; i++) {
            int idx = tid + 256 * i;        // float4 index 0..511
            int bb = idx >> 6, uu = (idx & 63) * 4;
            *(float4*)&hsh[bb][uu] = *(const float4*)(hp + (long long)bb * T_ * U_ + uu);
        }
    } else {
#pragma unroll
        for (int i = 0; i < 2; i++) {
            int idx = tid + 256 * i;
            int bb = idx >> 6, uu = (idx & 63) * 4;
            *(float4*)&hsh[bb][uu] = make_float4(0.f, 0.f, 0.f, 0.f);
        }
    }
    __syncthreads();

    float aR = 0.f, aZ = 0.f, aN = 0.f;
    if (t > 0) {
        const float4* w = g_wt4 + u;
#pragma unroll 8
        for (int k = 0; k < 256; k++) {
            float4 ww = w[k * 256];
            float hk = hsh[bl][k];
            aR += hk * ww.x;
            aZ += hk * ww.y;
            aN += hk * ww.z;
        }
    }
    int b = b0 + bl;
    long long xbase = ((long long)b * T_ + t) * 768;
    float r  = sigmoidf_(g_xg[xbase + u] + aR);
    float zz = sigmoidf_(g_xg[xbase + 256 + u] + aZ);
    float n  = tanhf(g_xg[xbase + 512 + u] + r * (aN + bhn[u]));
    float hp = hsh[bl][u];
    g_g[((long long)b * T_ + t) * U_ + u] = (1.f - zz) * n + zz * hp;
}

// ---------------- softmax, warp-per-row (T=288 = 9*32) ----------------
__global__ void __launch_bounds__(256) softmax_kernel(float* __restrict__ sAll)
{
    int lane = threadIdx.x & 31;
    long long row = (long long)blockIdx.x * 8 + (threadIdx.x >> 5);
    float* p = sAll + row * T_;
    float v[9];
    float mx = -1e30f;
#pragma unroll
    for (int j = 0; j < 9; j++) { v[j] = p[lane + 32 * j]; mx = fmaxf(mx, v[j]); }
    mx = warp_max(mx);
    float sum = 0.f;
#pragma unroll
    for (int j = 0; j < 9; j++) { v[j] = expf(v[j] - mx); sum += v[j]; }
    float inv = 1.f / warp_sum(sum);
#pragma unroll
    for (int j = 0; j < 9; j++) p[lane + 32 * j] = v[j] * inv;
}

// ---------------- head ----------------
__global__ void pool_kernel(const float* __restrict__ other)
{
    int b = blockIdx.x, u = threadIdx.x;
    float acc = 0.f;
    const float* xp = g_x + (long long)b * T_ * U_ + u;
#pragma unroll 4
    for (int t = 0; t < T_; t++) acc += xp[(long long)t * U_];
    g_c[b * (U_ + FO_) + u] = acc * (1.f / T_);
    if (u < FO_) g_c[b * (U_ + FO_) + U_ + u] = other[b * FO_ + u];
}

__global__ void mlp1_kernel(const float* __restrict__ W, const float* __restrict__ bias,
                            const float* __restrict__ s, const float* __restrict__ bb)
{
    __shared__ float c[320];
    __shared__ float sh[4];
    int b = blockIdx.x, j = threadIdx.x;
    for (int i = j; i < 320; i += 128) c[i] = g_c[b * 320 + i];
    __syncthreads();
    float acc = bias[j];
#pragma unroll 8
    for (int k = 0; k < 320; k++) acc += c[k] * W[k * 128 + j];
    acc = fmaxf(acc, 0.f);
    float m = blk_red<4, false>(acc, sh) * (1.f / 128.f);
    float d = acc - m;
    float var = blk_red<4, false>(d * d, sh) * (1.f / 128.f);
    g_h1[b * 128 + j] = d * rsqrtf(var + EPS_) * s[j] + bb[j];
}

__global__ void mlp2_kernel(const float* __restrict__ W, const float* __restrict__ bias,
                            const float* __restrict__ s, const float* __restrict__ bb)
{
    __shared__ float hbuf[128];
    __shared__ float sh[2];
    int b = blockIdx.x, j = threadIdx.x;
    for (int i = j; i < 128; i += 64) hbuf[i] = g_h1[b * 128 + i];
    __syncthreads();
    float acc = bias[j];
#pragma unroll 8
    for (int k = 0; k < 128; k++) acc += hbuf[k] * W[k * 64 + j];
    acc = fmaxf(acc, 0.f);
    float m = blk_red<2, false>(acc, sh) * (1.f / 64.f);
    float d = acc - m;
    float var = blk_red<2, false>(d * d, sh) * (1.f / 64.f);
    g_h2[b * 64 + j] = d * rsqrtf(var + EPS_) * s[j] + bb[j];
}

__global__ void out_kernel(const float* __restrict__ W, const float* __restrict__ ob,
                           float* __restrict__ o)
{
    int b = threadIdx.x;
    float acc = ob[0];
#pragma unroll 8
    for (int k = 0; k < 64; k++) acc += g_h2[b * 64 + k] * W[k];
    o[b] = acc;
}

// ---------------- launcher ----------------
extern "C" void kernel_launch(void* const* d_in, const int* in_sizes, int n_in,
                              void* d_out, int out_size)
{
    (void)in_sizes; (void)n_in; (void)out_size;
    const float* cgm   = (const float*)d_in[0];
    const float* other = (const float*)d_in[1];
    const float* d0W   = (const float*)d_in[2];
    const float* d0b   = (const float*)d_in[3];
    const float* ln0s  = (const float*)d_in[4];
    const float* ln0b  = (const float*)d_in[5];
    const float* gWi   = (const float*)d_in[6];
    const float* gbi   = (const float*)d_in[7];
    const float* gWh   = (const float*)d_in[8];
    const float* gbhn  = (const float*)d_in[9];
    const float* ln1s  = (const float*)d_in[10];
    const float* ln1b  = (const float*)d_in[11];
    const float* Wq    = (const float*)d_in[12];
    const float* bq    = (const float*)d_in[13];
    const float* Wk    = (const float*)d_in[14];
    const float* bk    = (const float*)d_in[15];
    const float* Wv    = (const float*)d_in[16];
    const float* bv    = (const float*)d_in[17];
    const float* Wo    = (const float*)d_in[18];
    const float* bo    = (const float*)d_in[19];
    const float* ln2s  = (const float*)d_in[20];
    const float* ln2b  = (const float*)d_in[21];
    const float* m1W   = (const float*)d_in[22];
    const float* m1b   = (const float*)d_in[23];
    const float* lm1s  = (const float*)d_in[24];
    const float* lm1b  = (const float*)d_in[25];
    const float* m2W   = (const float*)d_in[26];
    const float* m2b   = (const float*)d_in[27];
    const float* lm2s  = (const float*)d_in[28];
    const float* lm2b  = (const float*)d_in[29];
    const float* outW  = (const float*)d_in[30];
    const float* outb  = (const float*)d_in[31];

    float *px, *pxg, *pg, *pa, *ps;
    cudaGetSymbolAddress((void**)&px,  g_x);
    cudaGetSymbolAddress((void**)&pxg, g_xg);
    cudaGetSymbolAddress((void**)&pg,  g_g);
    cudaGetSymbolAddress((void**)&pa,  g_a);
    cudaGetSymbolAddress((void**)&ps,  g_s);
    float* pq = pxg;
    float* pk = pxg + (long long)BT_ * U_;
    float* pv = pxg + 2LL * BT_ * U_;

    // x = LN(cgm @ d0_W + d0_b)
    gemm_tf32<false, true><<<dim3(4, 288, 1), 256>>>(
        cgm, d0W, d0b, px, BT_, U_, FC_, FC_, U_, U_,
        0, 0, 0, 0, 0, 0, 1.f);
    ln_kernel<<<BT_ / 8, 256>>>(px, px, ln0s, ln0b, px, 2);

    for (int i = 0; i < 2; i++) {
        const float* Wi  = gWi  + (long long)i * U_ * 3 * U_;
        const float* bi  = gbi  + i * 3 * U_;
        const float* Wh  = gWh  + (long long)i * U_ * 3 * U_;
        const float* bhn = gbhn + i * U_;

        // xg = x @ Wi + bi   [BT,768]
        gemm_tf32<false, true><<<dim3(12, 288, 1), 256>>>(
            px, Wi, bi, pxg, BT_, 3 * U_, U_, U_, 3 * U_, 3 * U_,
            0, 0, 0, 0, 0, 0, 1.f);

        // repack Wh, then sequential scan
        repack_wh_kernel<<<256, 256>>>(Wh);
        for (int t = 0; t < T_; t++)
            gru_step_kernel<<<dim3(16, 8), 256>>>(bhn, t);

        // x = LN(g) + x
        ln_kernel<<<BT_ / 8, 256>>>(pg, px, ln1s + i * U_, ln1b + i * U_, px, 0);

        // q,k,v projections
        gemm_tf32<false, true><<<dim3(4, 288, 1), 256>>>(
            px, Wq + (long long)i * U_ * U_, bq + i * U_, pq,
            BT_, U_, U_, U_, U_, U_, 0, 0, 0, 0, 0, 0, 1.f);
        gemm_tf32<false, true><<<dim3(4, 288, 1), 256>>>(
            px, Wk + (long long)i * U_ * U_, bk + i * U_, pk,
            BT_, U_, U_, U_, U_, U_, 0, 0, 0, 0, 0, 0, 1.f);
        gemm_tf32<false, true><<<dim3(4, 288, 1), 256>>>(
            px, Wv + (long long)i * U_ * U_, bv + i * U_, pv,
            BT_, U_, U_, U_, U_, U_, 0, 0, 0, 0, 0, 0, 1.f);

        // scores = (Q @ K^T) / 8 per (b,h)
        gemm_tf32<true, false><<<dim3(5, 3, B_ * H_), 256>>>(
            pq, pk, nullptr, ps, T_, T_, HD_, U_, U_, T_,
            (long long)T_ * U_, HD_, (long long)T_ * U_, HD_,
            (long long)H_ * T_ * T_, (long long)T_ * T_, 0.125f);

        softmax_kernel<<<B_ * H_ * T_ / 8, 256>>>(ps);

        // context = P @ V per (b,h)
        gemm_tf32<false, false><<<dim3(1, 3, B_ * H_), 256>>>(
            ps, pv, nullptr, pa, T_, HD_, T_, T_, U_, U_,
            (long long)H_ * T_ * T_, (long long)T_ * T_,
            (long long)T_ * U_, HD_, (long long)T_ * U_, HD_, 1.f);

        // o-proj into g_g
        gemm_tf32<false, true><<<dim3(4, 288, 1), 256>>>(
            pa, Wo + (long long)i * U_ * U_, bo + i * U_, pg,
            BT_, U_, U_, U_, U_, U_, 0, 0, 0, 0, 0, 0, 1.f);

        // x = LN(o + x)
        ln_kernel<<<BT_ / 8, 256>>>(pg, px, ln2s + i * U_, ln2b + i * U_, px, 1);
    }

    // head
    pool_kernel<<<B_, 256>>>(other);
    mlp1_kernel<<<B_, 128>>>(m1W, m1b, lm1s, lm1b);
    mlp2_kernel<<<B_, 64>>>(m2W, m2b, lm2s, lm2b);
    out_kernel<<<1, B_>>>(outW, outb, (float*)d_out);
}